// round 14
// baseline (speedup 1.0000x reference)
#include <cuda_runtime.h>
#include <math.h>

#define BSZ   128
#define T     250
#define INDIM 700
#define INP   704
#define H     512
#define NOUT  20
#define HB    (H*BSZ)
#define NCTA  128

#define FIRE_OFF (BSZ*T*NOUT)      /* 640000 */
#define HID_OFF  (FIRE_OFF + 1)

// ---------------- device scratch (static, no allocations) ----------------
__device__ __align__(16) float g_xT  [(size_t)T*INP*BSZ];   // x transposed [t][i][b]
__device__ __align__(16) float g_W1T [INP*H];               // W1 transposed [i][j]
__device__ __align__(16) float g_xw1 [(size_t)T*H*BSZ];     // (x@W1^T)+b_i2h1, [t][j][b]
__device__ __align__(16) float g_m3h [(size_t)T*H*BSZ];     // m3 history [t][j][b]
// bit-packed spikes: [slot][b][jg] (byte jg holds spikes of neurons 4jg..4jg+3)
__device__ __align__(16) unsigned char g_pb1[2][BSZ*128];
__device__ __align__(16) unsigned char g_pb2[2][BSZ*128];
__device__ __align__(16) unsigned char g_pb3[2][BSZ*128];
__device__ float    g_cnt;                                  // fire-rate accumulator
__device__ unsigned g_barc;                                 // monotonic barrier counter

// ALIF update with LLVM FPOpFusion::Fast-style contraction (VALIDATED r9-r13).
#define ALIF(mm, ss, bb, hh, al, omal, rr, omrr) do {                      \
    bb = __fmaf_rn(rr, bb, __fmul_rn(omrr, ss));                           \
    float Bth_ = __fmaf_rn(1.8f, bb, 0.01f);                               \
    mm = __fmaf_rn(-Bth_, ss, __fmaf_rn(mm, al, __fmul_rn(omal, hh)));     \
    ss = (__fsub_rn(mm, Bth_) > 0.0f) ? 1.0f : 0.0f;                       \
} while (0)

// XLA:CPU GenerateVF32Exp (VALIDATED r9-r13)
__device__ __forceinline__ float exp_xla_fma(float v) {
    float x = fminf(v, 88.3762626647950f);
    x = fmaxf(x, -88.3762626647949f);
    float fx = floorf(__fmaf_rn(x, 1.44269504088896341f, 0.5f));
    float tmp = __fmul_rn(fx, 0.693359375f);
    float z   = __fmul_rn(fx, -2.12194440e-4f);
    x = __fsub_rn(x, tmp);
    x = __fsub_rn(x, z);
    z = __fmul_rn(x, x);
    float y = 1.9875691500E-4f;
    y = __fmaf_rn(y, x, 1.3981999507E-3f);
    y = __fmaf_rn(y, x, 8.3334519073E-3f);
    y = __fmaf_rn(y, x, 4.1665795894E-2f);
    y = __fmaf_rn(y, x, 1.6666665459E-1f);
    y = __fmaf_rn(y, x, 5.0000001201E-1f);
    y = __fmaf_rn(y, z, x);
    y = __fadd_rn(y, 1.0f);
    int n = (int)fx;
    return __fmul_rn(y, __int_as_float((n + 127) << 23));
}

// packed dual-lane FMA (bit-exact per lane) — used in k_xw1
__device__ __forceinline__ void fma2(unsigned long long& r,
                                     unsigned long long a,
                                     unsigned long long b) {
    asm("fma.rn.f32x2 %0, %1, %2, %0;" : "+l"(r) : "l"(a), "l"(b));
}
#define UNPACK2(lo, hi, v) \
    asm("mov.b64 {%0, %1}, %2;" : "=f"(lo), "=f"(hi) : "l"(v))

// predicated packed add: executed lane = RN(r+w) == fma(1,w,r);
// skipped = r unchanged == fma(0,w,r) (acc never -0 from +0 start under RN).
#define PADD2(r01, r23, bit, w01, w23)                                     \
    asm("{\n\t"                                                            \
        ".reg .pred p;\n\t"                                                \
        "setp.ne.u32 p, %2, 0;\n\t"                                        \
        "@p add.rn.f32x2 %0, %0, %3;\n\t"                                  \
        "@p add.rn.f32x2 %1, %1, %4;\n\t"                                  \
        "}"                                                                \
        : "+l"(r01), "+l"(r23)                                             \
        : "r"(bit), "l"(w01), "l"(w23))

// grid barrier: monotonic counter
__device__ __forceinline__ void gbar() {
    __syncthreads();
    if (threadIdx.x == 0) {
        __threadfence();
        unsigned r   = atomicAdd(&g_barc, 1u) + 1u;
        unsigned tgt = ((r + NCTA - 1u) / NCTA) * NCTA;
        while (*((volatile unsigned*)&g_barc) < tgt) { }
        __threadfence();
    }
    __syncthreads();
}

// single dot stream, predicated adds, double-buffered mask prefetch.
__device__ __forceinline__ void dot2p(const unsigned char* base,
                                      const float (*swm)[4],
                                      unsigned long long& r01,
                                      unsigned long long& r23) {
    const uint4* mp = (const uint4*)base;
    uint4 mq = __ldcg(&mp[0]);
#pragma unroll 1
    for (int wq = 0; wq < 8; wq++) {
        uint4 cur = mq;
        if (wq < 7) mq = __ldcg(&mp[wq + 1]);
        unsigned wds[4] = {cur.x, cur.y, cur.z, cur.w};
#pragma unroll
        for (int wi = 0; wi < 4; wi++) {
            unsigned wd = wds[wi];
#pragma unroll
            for (int d = 0; d < 4; d++) {
#pragma unroll
                for (int c = 0; c < 4; c++) {
                    int k = wq*64 + wi*16 + d*4 + c;
                    ulonglong2 wv = *(const ulonglong2*)&swm[k][0];
                    unsigned bit = wd & (1u << (8*d + c));
                    PADD2(r01, r23, bit, wv.x, wv.y);
                }
            }
        }
    }
}

// dual dot stream (two independent masks/matrices), interleaved per k for ILP.
__device__ __forceinline__ void dot2p_dual(const unsigned char* baseA,
                                           const unsigned char* baseB,
                                           const float (*swA)[4],
                                           const float (*swB)[4],
                                           unsigned long long& a01,
                                           unsigned long long& a23,
                                           unsigned long long& b01,
                                           unsigned long long& b23) {
    const uint4* mpA = (const uint4*)baseA;
    const uint4* mpB = (const uint4*)baseB;
    uint4 mqA = __ldcg(&mpA[0]);
    uint4 mqB = __ldcg(&mpB[0]);
#pragma unroll 1
    for (int wq = 0; wq < 8; wq++) {
        uint4 curA = mqA, curB = mqB;
        if (wq < 7) { mqA = __ldcg(&mpA[wq + 1]); mqB = __ldcg(&mpB[wq + 1]); }
        unsigned wdsA[4] = {curA.x, curA.y, curA.z, curA.w};
        unsigned wdsB[4] = {curB.x, curB.y, curB.z, curB.w};
#pragma unroll
        for (int wi = 0; wi < 4; wi++) {
            unsigned wdA = wdsA[wi], wdB = wdsB[wi];
#pragma unroll
            for (int d = 0; d < 4; d++) {
#pragma unroll
                for (int c = 0; c < 4; c++) {
                    int k = wq*64 + wi*16 + d*4 + c;
                    unsigned msel = 1u << (8*d + c);
                    ulonglong2 wa = *(const ulonglong2*)&swA[k][0];
                    PADD2(a01, a23, wdA & msel, wa.x, wa.y);
                    ulonglong2 wb = *(const ulonglong2*)&swB[k][0];
                    PADD2(b01, b23, wdB & msel, wb.x, wb.y);
                }
            }
        }
    }
}

// ---------------- kernel: transpose x -> g_xT [t][i][b] -------------------
__global__ void k_tr(const float* __restrict__ x) {
    __shared__ float tile[32][33];
    int i0 = blockIdx.x * 32, b0 = blockIdx.y * 32, t = blockIdx.z;
    int tx = threadIdx.x, ty = threadIdx.y;
    int i = i0 + tx;
#pragma unroll
    for (int r = 0; r < 4; r++) {
        int b = b0 + ty + r*8;
        float v = 0.0f;
        if (i < INDIM) v = x[((size_t)b*T + t)*INDIM + i];
        tile[ty + r*8][tx] = v;
    }
    __syncthreads();
#pragma unroll
    for (int r = 0; r < 4; r++) {
        int il = ty + r*8;
        g_xT[((size_t)t*INP + i0 + il)*BSZ + b0 + tx] = tile[tx][il];
    }
}

// ---------------- kernel: transpose W1 -> g_W1T ---------------------------
__global__ void k_w1t(const float* __restrict__ W1) {
    int idx = blockIdx.x * 256 + threadIdx.x;
    if (idx < INP*H) {
        int i = idx >> 9, j = idx & 511;
        g_W1T[idx] = (i < INDIM) ? W1[j*INDIM + i] : 0.0f;
    }
}

// ---------------- kernel: init packed spike buffers + fire counter --------
__global__ void k_init() {
    int idx = blockIdx.x * 256 + threadIdx.x;
    if (idx == 0) g_cnt = 0.0f;
    if (idx < (2*BSZ*128)/4) {
        ((unsigned*)g_pb1)[idx] = 0u;
        ((unsigned*)g_pb2)[idx] = 0u;
        ((unsigned*)g_pb3)[idx] = 0u;
    }
}

// ---------------- kernel: xw1 = (x@W1^T ascending-k chain)+b_i2h1 ---------
__global__ __launch_bounds__(256) void k_xw1(const float* __restrict__ b1) {
    __shared__ __align__(16) float xs[8*128];
    __shared__ __align__(16) float ws[8*128];
    int jg = blockIdx.x, t = blockIdx.y;
    int tid = threadIdx.x;
    int tx = tid & 15, ty = tid >> 4;

    unsigned long long acc2[8][4];
#pragma unroll
    for (int i = 0; i < 8; i++)
#pragma unroll
        for (int p = 0; p < 4; p++) acc2[i][p] = 0ULL;

    for (int k0 = 0; k0 < INP; k0 += 8) {
#pragma unroll
        for (int r = 0; r < 4; r++) {
            int lin = r*256 + tid;
            int kk = lin >> 7, c = lin & 127;
            xs[lin] = g_xT[((size_t)t*INP + k0 + kk)*BSZ + c];
            ws[lin] = g_W1T[(k0 + kk)*H + jg*128 + c];
        }
        __syncthreads();
#pragma unroll
        for (int kk = 0; kk < 8; kk++) {
            ulonglong2 xa = *(const ulonglong2*)&xs[kk*128 + tx*8];
            ulonglong2 xb = *(const ulonglong2*)&xs[kk*128 + tx*8 + 4];
            unsigned long long xp[4] = {xa.x, xa.y, xb.x, xb.y};
            float4 w0 = *(const float4*)&ws[kk*128 + ty*8];
            float4 w1 = *(const float4*)&ws[kk*128 + ty*8 + 4];
            float wf[8] = {w0.x,w0.y,w0.z,w0.w,w1.x,w1.y,w1.z,w1.w};
#pragma unroll
            for (int i = 0; i < 8; i++) {
                unsigned long long wd2;
                asm("mov.b64 %0, {%1, %1};" : "=l"(wd2) : "f"(wf[i]));
#pragma unroll
                for (int p = 0; p < 4; p++)
                    fma2(acc2[i][p], xp[p], wd2);
            }
        }
        __syncthreads();
    }
#pragma unroll
    for (int i = 0; i < 8; i++) {
        int jcol = jg*128 + ty*8 + i;
        float bias = __ldg(&b1[jcol]);
#pragma unroll
        for (int p = 0; p < 4; p++) {
            float lo, hi;
            UNPACK2(lo, hi, acc2[i][p]);
            g_xw1[((size_t)t*H + jcol)*BSZ + tx*8 + 2*p]     = __fadd_rn(lo, bias);
            g_xw1[((size_t)t*H + jcol)*BSZ + tx*8 + 2*p + 1] = __fadd_rn(hi, bias);
        }
    }
}

// ---------------- persistent pipelined ALIF scan ---------------------------
// 128 CTAs x 128 threads. CTA owns 4 neurons; thread owns batch column b.
// Stage s: l1(t=s) || l2(t=s-1) || l3(t=s-2); ONE grid barrier per stage.
__global__ __launch_bounds__(128) void k_scan(
    const float* __restrict__ Wh1, const float* __restrict__ bh1,
    const float* __restrict__ Wi2, const float* __restrict__ Wh2,
    const float* __restrict__ bi2, const float* __restrict__ bh2,
    const float* __restrict__ Wi3, const float* __restrict__ Wh3,
    const float* __restrict__ bi3, const float* __restrict__ bh3,
    const float* __restrict__ ta1, const float* __restrict__ ta2,
    const float* __restrict__ ta3, const float* __restrict__ tm1,
    const float* __restrict__ tm2, const float* __restrict__ tm3,
    float* __restrict__ dout)
{
    __shared__ __align__(16) float sw[5][H][4];   // 40KB, [mat][k][jl]
    __shared__ float red[4];
    const int tid = threadIdx.x;
    const int b   = tid;
    const int j0  = blockIdx.x * 4;
    const int jgrp = blockIdx.x;

    for (int i = tid; i < 5*H*4; i += 128) {
        int m = i >> 11, rem = i & 2047, k = rem >> 2, jl = rem & 3;
        const float* W = (m==0)?Wh1:(m==1)?Wi2:(m==2)?Wh2:(m==3)?Wi3:Wh3;
        sw[m][k][jl] = W[(size_t)(j0 + jl)*H + k];
    }
    __syncthreads();

    float al1[4], ro1[4], omal1[4], omro1[4];
    float al2[4], ro2[4], omal2[4], omro2[4];
    float al3[4], ro3[4], omal3[4], omro3[4];
    float bh1r[4], bi2r[4], bh2r[4], bi3r[4], bh3r[4];
#pragma unroll
    for (int jl = 0; jl < 4; jl++) {
        int j = j0 + jl;
        al1[jl] = exp_xla_fma(__fdiv_rn(-1.0f, __ldg(&tm1[j])));
        ro1[jl] = exp_xla_fma(__fdiv_rn(-1.0f, __ldg(&ta1[j])));
        al2[jl] = exp_xla_fma(__fdiv_rn(-1.0f, __ldg(&tm2[j])));
        ro2[jl] = exp_xla_fma(__fdiv_rn(-1.0f, __ldg(&ta2[j])));
        al3[jl] = exp_xla_fma(__fdiv_rn(-1.0f, __ldg(&tm3[j])));
        ro3[jl] = exp_xla_fma(__fdiv_rn(-1.0f, __ldg(&ta3[j])));
        omal1[jl] = __fsub_rn(1.0f, al1[jl]); omro1[jl] = __fsub_rn(1.0f, ro1[jl]);
        omal2[jl] = __fsub_rn(1.0f, al2[jl]); omro2[jl] = __fsub_rn(1.0f, ro2[jl]);
        omal3[jl] = __fsub_rn(1.0f, al3[jl]); omro3[jl] = __fsub_rn(1.0f, ro3[jl]);
        bh1r[jl] = __ldg(&bh1[j]);
        bi2r[jl] = __ldg(&bi2[j]); bh2r[jl] = __ldg(&bh2[j]);
        bi3r[jl] = __ldg(&bi3[j]); bh3r[jl] = __ldg(&bh3[j]);
    }

    float m1[4], b1s[4], s1r[4];
    float m2[4], b2s[4], s2r[4];
    float m3[4], b3s[4], s3r[4];
#pragma unroll
    for (int jl = 0; jl < 4; jl++) {
        m1[jl]=0.0f; b1s[jl]=0.01f; s1r[jl]=0.0f;
        m2[jl]=0.0f; b2s[jl]=0.01f; s2r[jl]=0.0f;
        m3[jl]=0.0f; b3s[jl]=0.01f; s3r[jl]=0.0f;
    }

    for (int s = 0; s < T + 2; s++) {
        // ---- layer 1: t = s ----
        if (s < T) {
            const int t = s;
            unsigned long long r01 = 0ULL, r23 = 0ULL;
            dot2p(&g_pb1[t & 1][(size_t)b*128], sw[0], r01, r23);
            float rr[4];
            UNPACK2(rr[0], rr[1], r01);
            UNPACK2(rr[2], rr[3], r23);
            unsigned msk = 0;
#pragma unroll
            for (int jl = 0; jl < 4; jl++) {
                int j = j0 + jl;
                float a = __fadd_rn(__fadd_rn(
                    __ldg(&g_xw1[((size_t)t*H + j)*BSZ + b]), rr[jl]), bh1r[jl]);
                ALIF(m1[jl], s1r[jl], b1s[jl], a,
                     al1[jl], omal1[jl], ro1[jl], omro1[jl]);
                if (s1r[jl] != 0.0f) msk |= (1u << jl);
            }
            __stcg(&g_pb1[(t+1) & 1][(size_t)b*128 + jgrp], (unsigned char)msk);
        }
        // ---- layer 2: t = s-1 ----
        if (s >= 1 && s <= T) {
            const int t = s - 1;
            unsigned long long i01=0ULL, i23=0ULL, h01=0ULL, h23=0ULL;
            dot2p_dual(&g_pb1[(t+1) & 1][(size_t)b*128],
                       &g_pb2[t & 1][(size_t)b*128],
                       sw[1], sw[2], i01, i23, h01, h23);
            float ri[4], rh[4];
            UNPACK2(ri[0], ri[1], i01); UNPACK2(ri[2], ri[3], i23);
            UNPACK2(rh[0], rh[1], h01); UNPACK2(rh[2], rh[3], h23);
            unsigned msk = 0;
#pragma unroll
            for (int jl = 0; jl < 4; jl++) {
                float a = __fadd_rn(__fadd_rn(__fadd_rn(ri[jl], bi2r[jl]),
                                              rh[jl]), bh2r[jl]);
                ALIF(m2[jl], s2r[jl], b2s[jl], a,
                     al2[jl], omal2[jl], ro2[jl], omro2[jl]);
                if (s2r[jl] != 0.0f) msk |= (1u << jl);
            }
            __stcg(&g_pb2[(t+1) & 1][(size_t)b*128 + jgrp], (unsigned char)msk);
        }
        // ---- layer 3: t = s-2 ----
        if (s >= 2) {
            const int t = s - 2;
            unsigned long long i01=0ULL, i23=0ULL, h01=0ULL, h23=0ULL;
            dot2p_dual(&g_pb2[(t+1) & 1][(size_t)b*128],
                       &g_pb3[t & 1][(size_t)b*128],
                       sw[3], sw[4], i01, i23, h01, h23);
            float ri[4], rh[4];
            UNPACK2(ri[0], ri[1], i01); UNPACK2(ri[2], ri[3], i23);
            UNPACK2(rh[0], rh[1], h01); UNPACK2(rh[2], rh[3], h23);
            unsigned msk = 0;
#pragma unroll
            for (int jl = 0; jl < 4; jl++) {
                int j = j0 + jl;
                float a = __fadd_rn(__fadd_rn(__fadd_rn(ri[jl], bi3r[jl]),
                                              rh[jl]), bh3r[jl]);
                ALIF(m3[jl], s3r[jl], b3s[jl], a,
                     al3[jl], omal3[jl], ro3[jl], omro3[jl]);
                if (s3r[jl] != 0.0f) msk |= (1u << jl);
                g_m3h[((size_t)t*H + j)*BSZ + b] = m3[jl];
                dout[HID_OFF + ((size_t)b*T + t)*H + j] = s3r[jl];
            }
            __stcg(&g_pb3[(t+1) & 1][(size_t)b*128 + jgrp], (unsigned char)msk);
        }
        gbar();
    }

    // fire rate: exact integer-valued float sums -> order-independent atomics
    float c = 0.0f;
#pragma unroll
    for (int jl = 0; jl < 4; jl++) c += s1r[jl] + s2r[jl] + s3r[jl];
#pragma unroll
    for (int o = 16; o > 0; o >>= 1) c += __shfl_xor_sync(0xffffffffu, c, o);
    if ((tid & 31) == 0) red[tid >> 5] = c;
    __syncthreads();
    if (tid == 0)
        atomicAdd(&g_cnt, red[0] + red[1] + red[2] + red[3]);
    gbar();
    if (blockIdx.x == 0 && tid == 0)
        dout[FIRE_OFF] = *((volatile float*)&g_cnt) / 196608.0f;
}

// ---------------- kernel: output = (m3@Wo^T chain from 0) + bo ------------
__global__ __launch_bounds__(128) void k_out(const float* __restrict__ Wo,
                                             const float* __restrict__ bo,
                                             float* __restrict__ dout) {
    int t = blockIdx.x, b = threadIdx.x;
    float acc[NOUT];
#pragma unroll
    for (int o = 0; o < NOUT; o++) acc[o] = 0.0f;
    const float* mp = &g_m3h[(size_t)t*H*BSZ + b];
    for (int k = 0; k < H; k++) {
        float v = mp[(size_t)k*BSZ];
#pragma unroll
        for (int o = 0; o < NOUT; o++)
            acc[o] = __fmaf_rn(v, __ldg(&Wo[o*H + k]), acc[o]);
    }
#pragma unroll
    for (int o = 0; o < NOUT; o++)
        dout[((size_t)b*T + t)*NOUT + o] = __fadd_rn(acc[o], __ldg(&bo[o]));
}

// ---------------- launch ---------------------------------------------------
extern "C" void kernel_launch(void* const* d_in, const int* in_sizes, int n_in,
                              void* d_out, int out_size) {
    const float* x      = (const float*)d_in[0];
    const float* W_i2h1 = (const float*)d_in[1];  const float* b_i2h1 = (const float*)d_in[2];
    const float* W_h2h1 = (const float*)d_in[3];  const float* b_h2h1 = (const float*)d_in[4];
    const float* W_i2h2 = (const float*)d_in[5];  const float* b_i2h2 = (const float*)d_in[6];
    const float* W_h2h2 = (const float*)d_in[7];  const float* b_h2h2 = (const float*)d_in[8];
    const float* W_i2h3 = (const float*)d_in[9];  const float* b_i2h3 = (const float*)d_in[10];
    const float* W_h2h3 = (const float*)d_in[11]; const float* b_h2h3 = (const float*)d_in[12];
    const float* W_h2o  = (const float*)d_in[13]; const float* b_h2o  = (const float*)d_in[14];
    const float* ta1 = (const float*)d_in[15];
    const float* ta2 = (const float*)d_in[16];
    const float* ta3 = (const float*)d_in[17];
    const float* tm1 = (const float*)d_in[18];
    const float* tm2 = (const float*)d_in[19];
    const float* tm3 = (const float*)d_in[20];
    float* out = (float*)d_out;

    k_tr  <<<dim3(22, 4, 250), dim3(32, 8)>>>(x);
    k_w1t <<<(INP*H + 255)/256, 256>>>(W_i2h1);
    k_init<<<(2*BSZ*128/4 + 255)/256, 256>>>();
    k_xw1 <<<dim3(4, 250), 256>>>(b_i2h1);

    k_scan<<<NCTA, 128>>>(W_h2h1, b_h2h1,
                          W_i2h2, W_h2h2, b_i2h2, b_h2h2,
                          W_i2h3, W_h2h3, b_i2h3, b_h2h3,
                          ta1, ta2, ta3, tm1, tm2, tm3, out);

    k_out <<<250, 128>>>(W_h2o, b_h2o, out);
}

// round 15
// speedup vs baseline: 1.4376x; 1.4376x over previous
#include <cuda_runtime.h>
#include <math.h>

#define BSZ   128
#define T     250
#define INDIM 700
#define INP   704
#define H     512
#define NOUT  20
#define HB    (H*BSZ)
#define NCTA  128

#define FIRE_OFF (BSZ*T*NOUT)      /* 640000 */
#define HID_OFF  (FIRE_OFF + 1)

// ---------------- device scratch (static, no allocations) ----------------
__device__ __align__(16) float g_xT  [(size_t)T*INP*BSZ];   // x transposed [t][i][b]
__device__ __align__(16) float g_W1T [INP*H];               // W1 transposed [i][j]
__device__ __align__(16) float g_xw1 [(size_t)T*H*BSZ];     // (x@W1^T)+b_i2h1, [t][j][b]
__device__ __align__(16) float g_m3h [(size_t)T*H*BSZ];     // m3 history [t][j][b]
// bit-packed spikes: [slot][b][jg] (byte jg holds spikes of neurons 4jg..4jg+3)
__device__ __align__(16) unsigned char g_pb1[2][BSZ*128];
__device__ __align__(16) unsigned char g_pb2[2][BSZ*128];
__device__ __align__(16) unsigned char g_pb3[2][BSZ*128];
__device__ float    g_cnt;                                  // fire-rate accumulator
__device__ unsigned g_barc;                                 // monotonic barrier counter

// ALIF update with LLVM FPOpFusion::Fast-style contraction (VALIDATED r9-r13).
#define ALIF(mm, ss, bb, hh, al, omal, rr, omrr) do {                      \
    bb = __fmaf_rn(rr, bb, __fmul_rn(omrr, ss));                           \
    float Bth_ = __fmaf_rn(1.8f, bb, 0.01f);                               \
    mm = __fmaf_rn(-Bth_, ss, __fmaf_rn(mm, al, __fmul_rn(omal, hh)));     \
    ss = (__fsub_rn(mm, Bth_) > 0.0f) ? 1.0f : 0.0f;                       \
} while (0)

// XLA:CPU GenerateVF32Exp (VALIDATED r9-r13)
__device__ __forceinline__ float exp_xla_fma(float v) {
    float x = fminf(v, 88.3762626647950f);
    x = fmaxf(x, -88.3762626647949f);
    float fx = floorf(__fmaf_rn(x, 1.44269504088896341f, 0.5f));
    float tmp = __fmul_rn(fx, 0.693359375f);
    float z   = __fmul_rn(fx, -2.12194440e-4f);
    x = __fsub_rn(x, tmp);
    x = __fsub_rn(x, z);
    z = __fmul_rn(x, x);
    float y = 1.9875691500E-4f;
    y = __fmaf_rn(y, x, 1.3981999507E-3f);
    y = __fmaf_rn(y, x, 8.3334519073E-3f);
    y = __fmaf_rn(y, x, 4.1665795894E-2f);
    y = __fmaf_rn(y, x, 1.6666665459E-1f);
    y = __fmaf_rn(y, x, 5.0000001201E-1f);
    y = __fmaf_rn(y, z, x);
    y = __fadd_rn(y, 1.0f);
    int n = (int)fx;
    return __fmul_rn(y, __int_as_float((n + 127) << 23));
}

// packed dual-lane FMA (bit-exact per lane)
__device__ __forceinline__ void fma2(unsigned long long& r,
                                     unsigned long long a,
                                     unsigned long long b) {
    asm("fma.rn.f32x2 %0, %1, %2, %0;" : "+l"(r) : "l"(a), "l"(b));
}
#define UNPACK2(lo, hi, v) \
    asm("mov.b64 {%0, %1}, %2;" : "=f"(lo), "=f"(hi) : "l"(v))

// grid barrier: monotonic counter (all 384 threads via syncthreads)
__device__ __forceinline__ void gbar() {
    __syncthreads();
    if (threadIdx.x == 0) {
        __threadfence();
        unsigned r   = atomicAdd(&g_barc, 1u) + 1u;
        unsigned tgt = ((r + NCTA - 1u) / NCTA) * NCTA;
        while (*((volatile unsigned*)&g_barc) < tgt) { }
        __threadfence();
    }
    __syncthreads();
}

// one dot stream over a packed spike vector (r13-validated select form,
// + mask double-buffer prefetch). Lane l accumulates fma(u, w[k][l], r[l])
// in ascending-k order — bit-exact.
__device__ __forceinline__ void dot2(const unsigned char* base,
                                     const float (*swm)[4],
                                     unsigned long long& r01,
                                     unsigned long long& r23) {
    const uint4* mp = (const uint4*)base;
    uint4 mq = __ldcg(&mp[0]);
#pragma unroll 1
    for (int wq = 0; wq < 8; wq++) {
        uint4 cur = mq;
        if (wq < 7) mq = __ldcg(&mp[wq + 1]);
        unsigned wds[4] = {cur.x, cur.y, cur.z, cur.w};
#pragma unroll
        for (int wi = 0; wi < 4; wi++) {
            unsigned wd = wds[wi];
#pragma unroll
            for (int d = 0; d < 4; d++) {
#pragma unroll
                for (int c = 0; c < 4; c++) {
                    int k = wq*64 + wi*16 + d*4 + c;
                    unsigned long long u2 =
                        (wd & (1u << (8*d + c))) ? 0x3F8000003F800000ULL : 0ULL;
                    ulonglong2 wv = *(const ulonglong2*)&swm[k][0];
                    fma2(r01, u2, wv.x);
                    fma2(r23, u2, wv.y);
                }
            }
        }
    }
}

// ---------------- kernel: transpose x -> g_xT [t][i][b] -------------------
__global__ void k_tr(const float* __restrict__ x) {
    __shared__ float tile[32][33];
    int i0 = blockIdx.x * 32, b0 = blockIdx.y * 32, t = blockIdx.z;
    int tx = threadIdx.x, ty = threadIdx.y;
    int i = i0 + tx;
#pragma unroll
    for (int r = 0; r < 4; r++) {
        int b = b0 + ty + r*8;
        float v = 0.0f;
        if (i < INDIM) v = x[((size_t)b*T + t)*INDIM + i];
        tile[ty + r*8][tx] = v;
    }
    __syncthreads();
#pragma unroll
    for (int r = 0; r < 4; r++) {
        int il = ty + r*8;
        g_xT[((size_t)t*INP + i0 + il)*BSZ + b0 + tx] = tile[tx][il];
    }
}

// ---------------- kernel: transpose W1 -> g_W1T ---------------------------
__global__ void k_w1t(const float* __restrict__ W1) {
    int idx = blockIdx.x * 256 + threadIdx.x;
    if (idx < INP*H) {
        int i = idx >> 9, j = idx & 511;
        g_W1T[idx] = (i < INDIM) ? W1[j*INDIM + i] : 0.0f;
    }
}

// ---------------- kernel: init packed spike buffers + fire counter --------
__global__ void k_init() {
    int idx = blockIdx.x * 256 + threadIdx.x;
    if (idx == 0) g_cnt = 0.0f;
    if (idx < (2*BSZ*128)/4) {
        ((unsigned*)g_pb1)[idx] = 0u;
        ((unsigned*)g_pb2)[idx] = 0u;
        ((unsigned*)g_pb3)[idx] = 0u;
    }
}

// ---------------- kernel: xw1 = (x@W1^T ascending-k chain)+b_i2h1 ---------
__global__ __launch_bounds__(256) void k_xw1(const float* __restrict__ b1) {
    __shared__ __align__(16) float xs[8*128];
    __shared__ __align__(16) float ws[8*128];
    int jg = blockIdx.x, t = blockIdx.y;
    int tid = threadIdx.x;
    int tx = tid & 15, ty = tid >> 4;

    unsigned long long acc2[8][4];
#pragma unroll
    for (int i = 0; i < 8; i++)
#pragma unroll
        for (int p = 0; p < 4; p++) acc2[i][p] = 0ULL;

    for (int k0 = 0; k0 < INP; k0 += 8) {
#pragma unroll
        for (int r = 0; r < 4; r++) {
            int lin = r*256 + tid;
            int kk = lin >> 7, c = lin & 127;
            xs[lin] = g_xT[((size_t)t*INP + k0 + kk)*BSZ + c];
            ws[lin] = g_W1T[(k0 + kk)*H + jg*128 + c];
        }
        __syncthreads();
#pragma unroll
        for (int kk = 0; kk < 8; kk++) {
            ulonglong2 xa = *(const ulonglong2*)&xs[kk*128 + tx*8];
            ulonglong2 xb = *(const ulonglong2*)&xs[kk*128 + tx*8 + 4];
            unsigned long long xp[4] = {xa.x, xa.y, xb.x, xb.y};
            float4 w0 = *(const float4*)&ws[kk*128 + ty*8];
            float4 w1 = *(const float4*)&ws[kk*128 + ty*8 + 4];
            float wf[8] = {w0.x,w0.y,w0.z,w0.w,w1.x,w1.y,w1.z,w1.w};
#pragma unroll
            for (int i = 0; i < 8; i++) {
                unsigned long long wd2;
                asm("mov.b64 %0, {%1, %1};" : "=l"(wd2) : "f"(wf[i]));
#pragma unroll
                for (int p = 0; p < 4; p++)
                    fma2(acc2[i][p], xp[p], wd2);
            }
        }
        __syncthreads();
    }
#pragma unroll
    for (int i = 0; i < 8; i++) {
        int jcol = jg*128 + ty*8 + i;
        float bias = __ldg(&b1[jcol]);
#pragma unroll
        for (int p = 0; p < 4; p++) {
            float lo, hi;
            UNPACK2(lo, hi, acc2[i][p]);
            g_xw1[((size_t)t*H + jcol)*BSZ + tx*8 + 2*p]     = __fadd_rn(lo, bias);
            g_xw1[((size_t)t*H + jcol)*BSZ + tx*8 + 2*p + 1] = __fadd_rn(hi, bias);
        }
    }
}

// ---------------- persistent pipelined ALIF scan (3 warp-groups) ----------
// 128 CTAs x 384 threads. wg = tid>>7 runs one layer; b = tid&127.
// Stage s: wg0=l1(t=s), wg1=l2(t=s-1), wg2=l3(t=s-2) IN PARALLEL.
// Slot schedule identical to r13 (all cross-layer data crosses the barrier).
__global__ __launch_bounds__(384) void k_scan(
    const float* __restrict__ Wh1, const float* __restrict__ bh1,
    const float* __restrict__ Wi2, const float* __restrict__ Wh2,
    const float* __restrict__ bi2, const float* __restrict__ bh2,
    const float* __restrict__ Wi3, const float* __restrict__ Wh3,
    const float* __restrict__ bi3, const float* __restrict__ bh3,
    const float* __restrict__ ta1, const float* __restrict__ ta2,
    const float* __restrict__ ta3, const float* __restrict__ tm1,
    const float* __restrict__ tm2, const float* __restrict__ tm3,
    float* __restrict__ dout)
{
    __shared__ __align__(16) float sw[5][H][4];   // 40KB, [mat][k][jl]
    __shared__ float red[12];
    const int tid = threadIdx.x;
    const int wg  = tid >> 7;          // 0,1,2 -> layer
    const int b   = tid & 127;         // batch column
    const int j0  = blockIdx.x * 4;
    const int jgrp = blockIdx.x;

    for (int i = tid; i < 5*H*4; i += 384) {
        int m = i >> 11, rem = i & 2047, k = rem >> 2, jl = rem & 3;
        const float* W = (m==0)?Wh1:(m==1)?Wi2:(m==2)?Wh2:(m==3)?Wi3:Wh3;
        sw[m][k][jl] = W[(size_t)(j0 + jl)*H + k];
    }
    __syncthreads();

    // per-wg layer constants
    const float* tmv = (wg==0) ? tm1 : (wg==1) ? tm2 : tm3;
    const float* tav = (wg==0) ? ta1 : (wg==1) ? ta2 : ta3;
    float al[4], ro[4], omal[4], omro[4];
    float bA[4], bB[4];   // wg0: bA=bh1 ; wg1/2: bA=bi, bB=bh
#pragma unroll
    for (int jl = 0; jl < 4; jl++) {
        int j = j0 + jl;
        al[jl] = exp_xla_fma(__fdiv_rn(-1.0f, __ldg(&tmv[j])));
        ro[jl] = exp_xla_fma(__fdiv_rn(-1.0f, __ldg(&tav[j])));
        omal[jl] = __fsub_rn(1.0f, al[jl]);
        omro[jl] = __fsub_rn(1.0f, ro[jl]);
        if (wg == 0)      { bA[jl] = __ldg(&bh1[j]); bB[jl] = 0.0f; }
        else if (wg == 1) { bA[jl] = __ldg(&bi2[j]); bB[jl] = __ldg(&bh2[j]); }
        else              { bA[jl] = __ldg(&bi3[j]); bB[jl] = __ldg(&bh3[j]); }
    }

    float mS[4], bS[4], sS[4];   // this wg's layer state
#pragma unroll
    for (int jl = 0; jl < 4; jl++) { mS[jl]=0.0f; bS[jl]=0.01f; sS[jl]=0.0f; }

    for (int s = 0; s < T + 2; s++) {
        if (wg == 0) {
            if (s < T) {
                const int t = s;
                unsigned long long r01 = 0ULL, r23 = 0ULL;
                dot2(&g_pb1[t & 1][(size_t)b*128], sw[0], r01, r23);
                float rr[4];
                UNPACK2(rr[0], rr[1], r01);
                UNPACK2(rr[2], rr[3], r23);
                unsigned msk = 0;
#pragma unroll
                for (int jl = 0; jl < 4; jl++) {
                    int j = j0 + jl;
                    float a = __fadd_rn(__fadd_rn(
                        __ldg(&g_xw1[((size_t)t*H + j)*BSZ + b]), rr[jl]), bA[jl]);
                    ALIF(mS[jl], sS[jl], bS[jl], a,
                         al[jl], omal[jl], ro[jl], omro[jl]);
                    if (sS[jl] != 0.0f) msk |= (1u << jl);
                }
                __stcg(&g_pb1[(t+1) & 1][(size_t)b*128 + jgrp], (unsigned char)msk);
            }
        } else if (wg == 1) {
            if (s >= 1 && s <= T) {
                const int t = s - 1;
                unsigned long long i01=0ULL, i23=0ULL, h01=0ULL, h23=0ULL;
                dot2(&g_pb1[(t+1) & 1][(size_t)b*128], sw[1], i01, i23);
                dot2(&g_pb2[t & 1][(size_t)b*128],     sw[2], h01, h23);
                float ri[4], rh[4];
                UNPACK2(ri[0], ri[1], i01); UNPACK2(ri[2], ri[3], i23);
                UNPACK2(rh[0], rh[1], h01); UNPACK2(rh[2], rh[3], h23);
                unsigned msk = 0;
#pragma unroll
                for (int jl = 0; jl < 4; jl++) {
                    float a = __fadd_rn(__fadd_rn(__fadd_rn(ri[jl], bA[jl]),
                                                  rh[jl]), bB[jl]);
                    ALIF(mS[jl], sS[jl], bS[jl], a,
                         al[jl], omal[jl], ro[jl], omro[jl]);
                    if (sS[jl] != 0.0f) msk |= (1u << jl);
                }
                __stcg(&g_pb2[(t+1) & 1][(size_t)b*128 + jgrp], (unsigned char)msk);
            }
        } else {
            if (s >= 2) {
                const int t = s - 2;
                unsigned long long i01=0ULL, i23=0ULL, h01=0ULL, h23=0ULL;
                dot2(&g_pb2[(t+1) & 1][(size_t)b*128], sw[3], i01, i23);
                dot2(&g_pb3[t & 1][(size_t)b*128],     sw[4], h01, h23);
                float ri[4], rh[4];
                UNPACK2(ri[0], ri[1], i01); UNPACK2(ri[2], ri[3], i23);
                UNPACK2(rh[0], rh[1], h01); UNPACK2(rh[2], rh[3], h23);
                unsigned msk = 0;
#pragma unroll
                for (int jl = 0; jl < 4; jl++) {
                    int j = j0 + jl;
                    float a = __fadd_rn(__fadd_rn(__fadd_rn(ri[jl], bA[jl]),
                                                  rh[jl]), bB[jl]);
                    ALIF(mS[jl], sS[jl], bS[jl], a,
                         al[jl], omal[jl], ro[jl], omro[jl]);
                    if (sS[jl] != 0.0f) msk |= (1u << jl);
                    g_m3h[((size_t)t*H + j)*BSZ + b] = mS[jl];
                    dout[HID_OFF + ((size_t)b*T + t)*H + j] = sS[jl];
                }
                __stcg(&g_pb3[(t+1) & 1][(size_t)b*128 + jgrp], (unsigned char)msk);
            }
        }
        gbar();
    }

    // fire rate: each wg contributes its layer's final spikes (exact ints)
    float c = 0.0f;
#pragma unroll
    for (int jl = 0; jl < 4; jl++) c += sS[jl];
#pragma unroll
    for (int o = 16; o > 0; o >>= 1) c += __shfl_xor_sync(0xffffffffu, c, o);
    if ((tid & 31) == 0) red[tid >> 5] = c;
    __syncthreads();
    if (tid == 0) {
        float s = 0.0f;
#pragma unroll
        for (int i = 0; i < 12; i++) s += red[i];
        atomicAdd(&g_cnt, s);
    }
    gbar();
    if (blockIdx.x == 0 && tid == 0)
        dout[FIRE_OFF] = *((volatile float*)&g_cnt) / 196608.0f;
}

// ---------------- kernel: output = (m3@Wo^T chain from 0) + bo ------------
__global__ __launch_bounds__(128) void k_out(const float* __restrict__ Wo,
                                             const float* __restrict__ bo,
                                             float* __restrict__ dout) {
    int t = blockIdx.x, b = threadIdx.x;
    float acc[NOUT];
#pragma unroll
    for (int o = 0; o < NOUT; o++) acc[o] = 0.0f;
    const float* mp = &g_m3h[(size_t)t*H*BSZ + b];
    for (int k = 0; k < H; k++) {
        float v = mp[(size_t)k*BSZ];
#pragma unroll
        for (int o = 0; o < NOUT; o++)
            acc[o] = __fmaf_rn(v, __ldg(&Wo[o*H + k]), acc[o]);
    }
#pragma unroll
    for (int o = 0; o < NOUT; o++)
        dout[((size_t)b*T + t)*NOUT + o] = __fadd_rn(acc[o], __ldg(&bo[o]));
}

// ---------------- launch ---------------------------------------------------
extern "C" void kernel_launch(void* const* d_in, const int* in_sizes, int n_in,
                              void* d_out, int out_size) {
    const float* x      = (const float*)d_in[0];
    const float* W_i2h1 = (const float*)d_in[1];  const float* b_i2h1 = (const float*)d_in[2];
    const float* W_h2h1 = (const float*)d_in[3];  const float* b_h2h1 = (const float*)d_in[4];
    const float* W_i2h2 = (const float*)d_in[5];  const float* b_i2h2 = (const float*)d_in[6];
    const float* W_h2h2 = (const float*)d_in[7];  const float* b_h2h2 = (const float*)d_in[8];
    const float* W_i2h3 = (const float*)d_in[9];  const float* b_i2h3 = (const float*)d_in[10];
    const float* W_h2h3 = (const float*)d_in[11]; const float* b_h2h3 = (const float*)d_in[12];
    const float* W_h2o  = (const float*)d_in[13]; const float* b_h2o  = (const float*)d_in[14];
    const float* ta1 = (const float*)d_in[15];
    const float* ta2 = (const float*)d_in[16];
    const float* ta3 = (const float*)d_in[17];
    const float* tm1 = (const float*)d_in[18];
    const float* tm2 = (const float*)d_in[19];
    const float* tm3 = (const float*)d_in[20];
    float* out = (float*)d_out;

    k_tr  <<<dim3(22, 4, 250), dim3(32, 8)>>>(x);
    k_w1t <<<(INP*H + 255)/256, 256>>>(W_i2h1);
    k_init<<<(2*BSZ*128/4 + 255)/256, 256>>>();
    k_xw1 <<<dim3(4, 250), 256>>>(b_i2h1);

    k_scan<<<NCTA, 384>>>(W_h2h1, b_h2h1,
                          W_i2h2, W_h2h2, b_i2h2, b_h2h2,
                          W_i2h3, W_h2h3, b_i2h3, b_h2h3,
                          ta1, ta2, ta3, tm1, tm2, tm3, out);

    k_out <<<250, 128>>>(W_h2o, b_h2o, out);
}

// round 16
// speedup vs baseline: 1.6155x; 1.1238x over previous
#include <cuda_runtime.h>
#include <math.h>

#define BSZ   128
#define T     250
#define INDIM 700
#define INP   704
#define H     512
#define NOUT  20
#define HB    (H*BSZ)
#define NCTA  128

#define FIRE_OFF (BSZ*T*NOUT)      /* 640000 */
#define HID_OFF  (FIRE_OFF + 1)

// ---------------- device scratch (static, no allocations) ----------------
__device__ __align__(16) float g_xT  [(size_t)T*INP*BSZ];   // x transposed [t][i][b]
__device__ __align__(16) float g_W1T [INP*H];               // W1 transposed [i][j]
__device__ __align__(16) float g_xw1 [(size_t)T*H*BSZ];     // (x@W1^T)+b_i2h1, [t][j][b]
__device__ __align__(16) float g_m3h [(size_t)T*H*BSZ];     // m3 history [t][j][b]
// bit-packed spikes, coalesced layout: [slot][q][b][16B], q = jg>>4.
// byte (b, jg) lives at ((jg>>4)*BSZ + b)*16 + (jg&15); bit jl of that byte
// is neuron 4*jg+jl. Same bits as r15, different placement only.
__device__ __align__(16) unsigned char g_pb1[2][8*BSZ*16];
__device__ __align__(16) unsigned char g_pb2[2][8*BSZ*16];
__device__ __align__(16) unsigned char g_pb3[2][8*BSZ*16];
__device__ float    g_cnt;                                  // fire-rate accumulator
__device__ unsigned g_barc;                                 // monotonic barrier counter

// ALIF update with LLVM FPOpFusion::Fast-style contraction (VALIDATED r9-r15).
#define ALIF(mm, ss, bb, hh, al, omal, rr, omrr) do {                      \
    bb = __fmaf_rn(rr, bb, __fmul_rn(omrr, ss));                           \
    float Bth_ = __fmaf_rn(1.8f, bb, 0.01f);                               \
    mm = __fmaf_rn(-Bth_, ss, __fmaf_rn(mm, al, __fmul_rn(omal, hh)));     \
    ss = (__fsub_rn(mm, Bth_) > 0.0f) ? 1.0f : 0.0f;                       \
} while (0)

// XLA:CPU GenerateVF32Exp (VALIDATED r9-r15)
__device__ __forceinline__ float exp_xla_fma(float v) {
    float x = fminf(v, 88.3762626647950f);
    x = fmaxf(x, -88.3762626647949f);
    float fx = floorf(__fmaf_rn(x, 1.44269504088896341f, 0.5f));
    float tmp = __fmul_rn(fx, 0.693359375f);
    float z   = __fmul_rn(fx, -2.12194440e-4f);
    x = __fsub_rn(x, tmp);
    x = __fsub_rn(x, z);
    z = __fmul_rn(x, x);
    float y = 1.9875691500E-4f;
    y = __fmaf_rn(y, x, 1.3981999507E-3f);
    y = __fmaf_rn(y, x, 8.3334519073E-3f);
    y = __fmaf_rn(y, x, 4.1665795894E-2f);
    y = __fmaf_rn(y, x, 1.6666665459E-1f);
    y = __fmaf_rn(y, x, 5.0000001201E-1f);
    y = __fmaf_rn(y, z, x);
    y = __fadd_rn(y, 1.0f);
    int n = (int)fx;
    return __fmul_rn(y, __int_as_float((n + 127) << 23));
}

// packed dual-lane FMA (bit-exact per lane)
__device__ __forceinline__ void fma2(unsigned long long& r,
                                     unsigned long long a,
                                     unsigned long long b) {
    asm("fma.rn.f32x2 %0, %1, %2, %0;" : "+l"(r) : "l"(a), "l"(b));
}
#define UNPACK2(lo, hi, v) \
    asm("mov.b64 {%0, %1}, %2;" : "=f"(lo), "=f"(hi) : "l"(v))

// grid barrier: release-atomic + acquire-poll. No membar.gl / CCTL.IVALL:
// all cross-CTA data moves through L2 (__stcg/__ldcg), release orders the
// prior weak stores, acquire orders subsequent loads. Monotonic counter.
__device__ __forceinline__ void gbar() {
    __syncthreads();
    if (threadIdx.x == 0) {
        unsigned r;
        asm volatile("atom.release.gpu.global.add.u32 %0, [%1], 1;"
                     : "=r"(r) : "l"(&g_barc) : "memory");
        unsigned tgt = ((r + 1u + NCTA - 1u) / NCTA) * NCTA;
        unsigned v;
        do {
            asm volatile("ld.acquire.gpu.global.u32 %0, [%1];"
                         : "=r"(v) : "l"(&g_barc) : "memory");
        } while (v < tgt);
    }
    __syncthreads();
}

// one dot stream over a packed spike vector (coalesced [q][b][16B] layout).
// Lane l accumulates fma(u, w[k][l], r[l]) ascending-k — bit-exact vs r15.
__device__ __forceinline__ void dot2(const unsigned char* base, int b,
                                     const float (*swm)[4],
                                     unsigned long long& r01,
                                     unsigned long long& r23) {
    const uint4* mp = (const uint4*)base;
    uint4 mq = __ldcg(&mp[b]);
#pragma unroll 1
    for (int wq = 0; wq < 8; wq++) {
        uint4 cur = mq;
        if (wq < 7) mq = __ldcg(&mp[(wq + 1)*BSZ + b]);
        unsigned wds[4] = {cur.x, cur.y, cur.z, cur.w};
#pragma unroll
        for (int wi = 0; wi < 4; wi++) {
            unsigned wd = wds[wi];
#pragma unroll
            for (int d = 0; d < 4; d++) {
#pragma unroll
                for (int c = 0; c < 4; c++) {
                    int k = wq*64 + wi*16 + d*4 + c;
                    unsigned long long u2 =
                        (wd & (1u << (8*d + c))) ? 0x3F8000003F800000ULL : 0ULL;
                    ulonglong2 wv = *(const ulonglong2*)&swm[k][0];
                    fma2(r01, u2, wv.x);
                    fma2(r23, u2, wv.y);
                }
            }
        }
    }
}

// ---------------- kernel: transpose x -> g_xT [t][i][b] -------------------
__global__ void k_tr(const float* __restrict__ x) {
    __shared__ float tile[32][33];
    int i0 = blockIdx.x * 32, b0 = blockIdx.y * 32, t = blockIdx.z;
    int tx = threadIdx.x, ty = threadIdx.y;
    int i = i0 + tx;
#pragma unroll
    for (int r = 0; r < 4; r++) {
        int b = b0 + ty + r*8;
        float v = 0.0f;
        if (i < INDIM) v = x[((size_t)b*T + t)*INDIM + i];
        tile[ty + r*8][tx] = v;
    }
    __syncthreads();
#pragma unroll
    for (int r = 0; r < 4; r++) {
        int il = ty + r*8;
        g_xT[((size_t)t*INP + i0 + il)*BSZ + b0 + tx] = tile[tx][il];
    }
}

// ---------------- kernel: transpose W1 -> g_W1T ---------------------------
__global__ void k_w1t(const float* __restrict__ W1) {
    int idx = blockIdx.x * 256 + threadIdx.x;
    if (idx < INP*H) {
        int i = idx >> 9, j = idx & 511;
        g_W1T[idx] = (i < INDIM) ? W1[j*INDIM + i] : 0.0f;
    }
}

// ---------------- kernel: init packed spike buffers + fire counter --------
__global__ void k_init() {
    int idx = blockIdx.x * 256 + threadIdx.x;
    if (idx == 0) g_cnt = 0.0f;
    if (idx < (2*8*BSZ*16)/4) {
        ((unsigned*)g_pb1)[idx] = 0u;
        ((unsigned*)g_pb2)[idx] = 0u;
        ((unsigned*)g_pb3)[idx] = 0u;
    }
}

// ---------------- kernel: xw1 = (x@W1^T ascending-k chain)+b_i2h1 ---------
// double-buffered smem ping-pong (one __syncthreads per k-block).
__global__ __launch_bounds__(256) void k_xw1(const float* __restrict__ b1) {
    __shared__ __align__(16) float xs[2][8*128];
    __shared__ __align__(16) float ws[2][8*128];
    int jg = blockIdx.x, t = blockIdx.y;
    int tid = threadIdx.x;
    int tx = tid & 15, ty = tid >> 4;

    unsigned long long acc2[8][4];
#pragma unroll
    for (int i = 0; i < 8; i++)
#pragma unroll
        for (int p = 0; p < 4; p++) acc2[i][p] = 0ULL;

    // preload block 0
#pragma unroll
    for (int r = 0; r < 4; r++) {
        int lin = r*256 + tid;
        int kk = lin >> 7, c = lin & 127;
        xs[0][lin] = g_xT[((size_t)t*INP + kk)*BSZ + c];
        ws[0][lin] = g_W1T[kk*H + jg*128 + c];
    }
    __syncthreads();

    for (int it = 0; it < INP/8; it++) {
        int cur = it & 1, nxt = cur ^ 1;
        if (it < INP/8 - 1) {
            int k0 = (it + 1)*8;
#pragma unroll
            for (int r = 0; r < 4; r++) {
                int lin = r*256 + tid;
                int kk = lin >> 7, c = lin & 127;
                xs[nxt][lin] = g_xT[((size_t)t*INP + k0 + kk)*BSZ + c];
                ws[nxt][lin] = g_W1T[(k0 + kk)*H + jg*128 + c];
            }
        }
#pragma unroll
        for (int kk = 0; kk < 8; kk++) {
            ulonglong2 xa = *(const ulonglong2*)&xs[cur][kk*128 + tx*8];
            ulonglong2 xb = *(const ulonglong2*)&xs[cur][kk*128 + tx*8 + 4];
            unsigned long long xp[4] = {xa.x, xa.y, xb.x, xb.y};
            float4 w0 = *(const float4*)&ws[cur][kk*128 + ty*8];
            float4 w1 = *(const float4*)&ws[cur][kk*128 + ty*8 + 4];
            float wf[8] = {w0.x,w0.y,w0.z,w0.w,w1.x,w1.y,w1.z,w1.w};
#pragma unroll
            for (int i = 0; i < 8; i++) {
                unsigned long long wd2;
                asm("mov.b64 %0, {%1, %1};" : "=l"(wd2) : "f"(wf[i]));
#pragma unroll
                for (int p = 0; p < 4; p++)
                    fma2(acc2[i][p], xp[p], wd2);
            }
        }
        __syncthreads();
    }
#pragma unroll
    for (int i = 0; i < 8; i++) {
        int jcol = jg*128 + ty*8 + i;
        float bias = __ldg(&b1[jcol]);
#pragma unroll
        for (int p = 0; p < 4; p++) {
            float lo, hi;
            UNPACK2(lo, hi, acc2[i][p]);
            g_xw1[((size_t)t*H + jcol)*BSZ + tx*8 + 2*p]     = __fadd_rn(lo, bias);
            g_xw1[((size_t)t*H + jcol)*BSZ + tx*8 + 2*p + 1] = __fadd_rn(hi, bias);
        }
    }
}

// ---------------- persistent pipelined ALIF scan (3 warp-groups) ----------
// 128 CTAs x 384 threads. wg = tid>>7 runs one layer; b = tid&127.
// Stage s: wg0=l1(t=s), wg1=l2(t=s-1), wg2=l3(t=s-2) IN PARALLEL.
__global__ __launch_bounds__(384) void k_scan(
    const float* __restrict__ Wh1, const float* __restrict__ bh1,
    const float* __restrict__ Wi2, const float* __restrict__ Wh2,
    const float* __restrict__ bi2, const float* __restrict__ bh2,
    const float* __restrict__ Wi3, const float* __restrict__ Wh3,
    const float* __restrict__ bi3, const float* __restrict__ bh3,
    const float* __restrict__ ta1, const float* __restrict__ ta2,
    const float* __restrict__ ta3, const float* __restrict__ tm1,
    const float* __restrict__ tm2, const float* __restrict__ tm3,
    float* __restrict__ dout)
{
    __shared__ __align__(16) float sw[5][H][4];   // 40KB, [mat][k][jl]
    __shared__ float red[12];
    const int tid = threadIdx.x;
    const int wg  = tid >> 7;          // 0,1,2 -> layer
    const int b   = tid & 127;         // batch column
    const int j0  = blockIdx.x * 4;
    const int jgrp = blockIdx.x;
    // coalesced mask byte offset for this CTA's nibble
    const unsigned moff = (unsigned)(((jgrp >> 4)*BSZ + b)*16 + (jgrp & 15));

    for (int i = tid; i < 5*H*4; i += 384) {
        int m = i >> 11, rem = i & 2047, k = rem >> 2, jl = rem & 3;
        const float* W = (m==0)?Wh1:(m==1)?Wi2:(m==2)?Wh2:(m==3)?Wi3:Wh3;
        sw[m][k][jl] = W[(size_t)(j0 + jl)*H + k];
    }
    __syncthreads();

    // per-wg layer constants
    const float* tmv = (wg==0) ? tm1 : (wg==1) ? tm2 : tm3;
    const float* tav = (wg==0) ? ta1 : (wg==1) ? ta2 : ta3;
    float al[4], ro[4], omal[4], omro[4];
    float bA[4], bB[4];
#pragma unroll
    for (int jl = 0; jl < 4; jl++) {
        int j = j0 + jl;
        al[jl] = exp_xla_fma(__fdiv_rn(-1.0f, __ldg(&tmv[j])));
        ro[jl] = exp_xla_fma(__fdiv_rn(-1.0f, __ldg(&tav[j])));
        omal[jl] = __fsub_rn(1.0f, al[jl]);
        omro[jl] = __fsub_rn(1.0f, ro[jl]);
        if (wg == 0)      { bA[jl] = __ldg(&bh1[j]); bB[jl] = 0.0f; }
        else if (wg == 1) { bA[jl] = __ldg(&bi2[j]); bB[jl] = __ldg(&bh2[j]); }
        else              { bA[jl] = __ldg(&bi3[j]); bB[jl] = __ldg(&bh3[j]); }
    }

    float mS[4], bS[4], sS[4];
#pragma unroll
    for (int jl = 0; jl < 4; jl++) { mS[jl]=0.0f; bS[jl]=0.01f; sS[jl]=0.0f; }

    for (int s = 0; s < T + 2; s++) {
        if (wg == 0) {
            if (s < T) {
                const int t = s;
                unsigned long long r01 = 0ULL, r23 = 0ULL;
                dot2(g_pb1[t & 1], b, sw[0], r01, r23);
                float rr[4];
                UNPACK2(rr[0], rr[1], r01);
                UNPACK2(rr[2], rr[3], r23);
                unsigned msk = 0;
#pragma unroll
                for (int jl = 0; jl < 4; jl++) {
                    int j = j0 + jl;
                    float a = __fadd_rn(__fadd_rn(
                        __ldg(&g_xw1[((size_t)t*H + j)*BSZ + b]), rr[jl]), bA[jl]);
                    ALIF(mS[jl], sS[jl], bS[jl], a,
                         al[jl], omal[jl], ro[jl], omro[jl]);
                    if (sS[jl] != 0.0f) msk |= (1u << jl);
                }
                __stcg(&g_pb1[(t+1) & 1][moff], (unsigned char)msk);
            }
        } else if (wg == 1) {
            if (s >= 1 && s <= T) {
                const int t = s - 1;
                unsigned long long i01=0ULL, i23=0ULL, h01=0ULL, h23=0ULL;
                dot2(g_pb1[(t+1) & 1], b, sw[1], i01, i23);
                dot2(g_pb2[t & 1],     b, sw[2], h01, h23);
                float ri[4], rh[4];
                UNPACK2(ri[0], ri[1], i01); UNPACK2(ri[2], ri[3], i23);
                UNPACK2(rh[0], rh[1], h01); UNPACK2(rh[2], rh[3], h23);
                unsigned msk = 0;
#pragma unroll
                for (int jl = 0; jl < 4; jl++) {
                    float a = __fadd_rn(__fadd_rn(__fadd_rn(ri[jl], bA[jl]),
                                                  rh[jl]), bB[jl]);
                    ALIF(mS[jl], sS[jl], bS[jl], a,
                         al[jl], omal[jl], ro[jl], omro[jl]);
                    if (sS[jl] != 0.0f) msk |= (1u << jl);
                }
                __stcg(&g_pb2[(t+1) & 1][moff], (unsigned char)msk);
            }
        } else {
            if (s >= 2) {
                const int t = s - 2;
                unsigned long long i01=0ULL, i23=0ULL, h01=0ULL, h23=0ULL;
                dot2(g_pb2[(t+1) & 1], b, sw[3], i01, i23);
                dot2(g_pb3[t & 1],     b, sw[4], h01, h23);
                float ri[4], rh[4];
                UNPACK2(ri[0], ri[1], i01); UNPACK2(ri[2], ri[3], i23);
                UNPACK2(rh[0], rh[1], h01); UNPACK2(rh[2], rh[3], h23);
                unsigned msk = 0;
#pragma unroll
                for (int jl = 0; jl < 4; jl++) {
                    int j = j0 + jl;
                    float a = __fadd_rn(__fadd_rn(__fadd_rn(ri[jl], bA[jl]),
                                                  rh[jl]), bB[jl]);
                    ALIF(mS[jl], sS[jl], bS[jl], a,
                         al[jl], omal[jl], ro[jl], omro[jl]);
                    if (sS[jl] != 0.0f) msk |= (1u << jl);
                    g_m3h[((size_t)t*H + j)*BSZ + b] = mS[jl];
                    dout[HID_OFF + ((size_t)b*T + t)*H + j] = sS[jl];
                }
                __stcg(&g_pb3[(t+1) & 1][moff], (unsigned char)msk);
            }
        }
        gbar();
    }

    // fire rate: each wg contributes its layer's final spikes (exact ints)
    float c = 0.0f;
#pragma unroll
    for (int jl = 0; jl < 4; jl++) c += sS[jl];
#pragma unroll
    for (int o = 16; o > 0; o >>= 1) c += __shfl_xor_sync(0xffffffffu, c, o);
    if ((tid & 31) == 0) red[tid >> 5] = c;
    __syncthreads();
    if (tid == 0) {
        float s = 0.0f;
#pragma unroll
        for (int i = 0; i < 12; i++) s += red[i];
        atomicAdd(&g_cnt, s);
    }
    gbar();
    if (blockIdx.x == 0 && tid == 0)
        dout[FIRE_OFF] = *((volatile float*)&g_cnt) / 196608.0f;
}

// ---------------- kernel: output = (m3@Wo^T chain from 0) + bo ------------
__global__ __launch_bounds__(128) void k_out(const float* __restrict__ Wo,
                                             const float* __restrict__ bo,
                                             float* __restrict__ dout) {
    int t = blockIdx.x, b = threadIdx.x;
    float acc[NOUT];
#pragma unroll
    for (int o = 0; o < NOUT; o++) acc[o] = 0.0f;
    const float* mp = &g_m3h[(size_t)t*H*BSZ + b];
    for (int k = 0; k < H; k++) {
        float v = mp[(size_t)k*BSZ];
#pragma unroll
        for (int o = 0; o < NOUT; o++)
            acc[o] = __fmaf_rn(v, __ldg(&Wo[o*H + k]), acc[o]);
    }
#pragma unroll
    for (int o = 0; o < NOUT; o++)
        dout[((size_t)b*T + t)*NOUT + o] = __fadd_rn(acc[o], __ldg(&bo[o]));
}

// ---------------- launch ---------------------------------------------------
extern "C" void kernel_launch(void* const* d_in, const int* in_sizes, int n_in,
                              void* d_out, int out_size) {
    const float* x      = (const float*)d_in[0];
    const float* W_i2h1 = (const float*)d_in[1];  const float* b_i2h1 = (const float*)d_in[2];
    const float* W_h2h1 = (const float*)d_in[3];  const float* b_h2h1 = (const float*)d_in[4];
    const float* W_i2h2 = (const float*)d_in[5];  const float* b_i2h2 = (const float*)d_in[6];
    const float* W_h2h2 = (const float*)d_in[7];  const float* b_h2h2 = (const float*)d_in[8];
    const float* W_i2h3 = (const float*)d_in[9];  const float* b_i2h3 = (const float*)d_in[10];
    const float* W_h2h3 = (const float*)d_in[11]; const float* b_h2h3 = (const float*)d_in[12];
    const float* W_h2o  = (const float*)d_in[13]; const float* b_h2o  = (const float*)d_in[14];
    const float* ta1 = (const float*)d_in[15];
    const float* ta2 = (const float*)d_in[16];
    const float* ta3 = (const float*)d_in[17];
    const float* tm1 = (const float*)d_in[18];
    const float* tm2 = (const float*)d_in[19];
    const float* tm3 = (const float*)d_in[20];
    float* out = (float*)d_out;

    k_tr  <<<dim3(22, 4, 250), dim3(32, 8)>>>(x);
    k_w1t <<<(INP*H + 255)/256, 256>>>(W_i2h1);
    k_init<<<(2*8*BSZ*16/4 + 255)/256, 256>>>();
    k_xw1 <<<dim3(4, 250), 256>>>(b_i2h1);

    k_scan<<<NCTA, 384>>>(W_h2h1, b_h2h1,
                          W_i2h2, W_h2h2, b_i2h2, b_h2h2,
                          W_i2h3, W_h2h3, b_i2h3, b_h2h3,
                          ta1, ta2, ta3, tm1, tm2, tm3, out);

    k_out <<<250, 128>>>(W_h2o, b_h2o, out);
}

// round 17
// speedup vs baseline: 1.6182x; 1.0016x over previous
#include <cuda_runtime.h>
#include <math.h>

#define BSZ   128
#define T     250
#define INDIM 700
#define INP   704
#define H     512
#define NOUT  20
#define HB    (H*BSZ)
#define NCTA  128

#define FIRE_OFF (BSZ*T*NOUT)      /* 640000 */
#define HID_OFF  (FIRE_OFF + 1)

// ---------------- device scratch (static, no allocations) ----------------
__device__ __align__(16) float g_xT  [(size_t)T*INP*BSZ];   // x transposed [t][i][b]
__device__ __align__(16) float g_W1T [INP*H];               // W1 transposed [i][j]
__device__ __align__(16) float g_xw1 [(size_t)T*H*BSZ];     // (x@W1^T)+b_i2h1, [t][j][b]
__device__ __align__(16) float g_m3h [(size_t)T*H*BSZ];     // m3 history [t][j][b]
// bit-packed spikes, coalesced: [slot][q][b][16B], byte (b,jg) at
// ((jg>>4)*BSZ + b)*16 + (jg&15); bit jl = neuron 4*jg+jl.
__device__ __align__(16) unsigned char g_pb1[2][8*BSZ*16];
__device__ __align__(16) unsigned char g_pb2[2][8*BSZ*16];
__device__ __align__(16) unsigned char g_pb3[2][8*BSZ*16];
__device__ float    g_cnt;                                  // fire-rate accumulator
__device__ unsigned g_barc;                                 // monotonic barrier counter

// ALIF update with LLVM FPOpFusion::Fast-style contraction (VALIDATED r9-r16).
#define ALIF(mm, ss, bb, hh, al, omal, rr, omrr) do {                      \
    bb = __fmaf_rn(rr, bb, __fmul_rn(omrr, ss));                           \
    float Bth_ = __fmaf_rn(1.8f, bb, 0.01f);                               \
    mm = __fmaf_rn(-Bth_, ss, __fmaf_rn(mm, al, __fmul_rn(omal, hh)));     \
    ss = (__fsub_rn(mm, Bth_) > 0.0f) ? 1.0f : 0.0f;                       \
} while (0)

// XLA:CPU GenerateVF32Exp (VALIDATED r9-r16)
__device__ __forceinline__ float exp_xla_fma(float v) {
    float x = fminf(v, 88.3762626647950f);
    x = fmaxf(x, -88.3762626647949f);
    float fx = floorf(__fmaf_rn(x, 1.44269504088896341f, 0.5f));
    float tmp = __fmul_rn(fx, 0.693359375f);
    float z   = __fmul_rn(fx, -2.12194440e-4f);
    x = __fsub_rn(x, tmp);
    x = __fsub_rn(x, z);
    z = __fmul_rn(x, x);
    float y = 1.9875691500E-4f;
    y = __fmaf_rn(y, x, 1.3981999507E-3f);
    y = __fmaf_rn(y, x, 8.3334519073E-3f);
    y = __fmaf_rn(y, x, 4.1665795894E-2f);
    y = __fmaf_rn(y, x, 1.6666665459E-1f);
    y = __fmaf_rn(y, x, 5.0000001201E-1f);
    y = __fmaf_rn(y, z, x);
    y = __fadd_rn(y, 1.0f);
    int n = (int)fx;
    return __fmul_rn(y, __int_as_float((n + 127) << 23));
}

// packed dual-lane FMA (bit-exact per lane)
__device__ __forceinline__ void fma2(unsigned long long& r,
                                     unsigned long long a,
                                     unsigned long long b) {
    asm("fma.rn.f32x2 %0, %1, %2, %0;" : "+l"(r) : "l"(a), "l"(b));
}
#define UNPACK2(lo, hi, v) \
    asm("mov.b64 {%0, %1}, %2;" : "=f"(lo), "=f"(hi) : "l"(v))

// grid barrier: release-atomic + acquire-poll (no L1 flush; spikes are L2)
__device__ __forceinline__ void gbar() {
    __syncthreads();
    if (threadIdx.x == 0) {
        unsigned r;
        asm volatile("atom.release.gpu.global.add.u32 %0, [%1], 1;"
                     : "=r"(r) : "l"(&g_barc) : "memory");
        unsigned tgt = ((r + 1u + NCTA - 1u) / NCTA) * NCTA;
        unsigned v;
        do {
            asm volatile("ld.acquire.gpu.global.u32 %0, [%1];"
                         : "=r"(v) : "l"(&g_barc) : "memory");
        } while (v < tgt);
    }
    __syncthreads();
}

// one dot stream over a packed spike vector (coalesced [q][b][16B] layout).
// Lane l accumulates fma(u, w[k][l], r[l]) ascending-k — bit-exact.
__device__ __forceinline__ void dot2(const unsigned char* base, int b,
                                     const float (*swm)[4],
                                     unsigned long long& r01,
                                     unsigned long long& r23) {
    const uint4* mp = (const uint4*)base;
    uint4 mq = __ldcg(&mp[b]);
#pragma unroll 1
    for (int wq = 0; wq < 8; wq++) {
        uint4 cur = mq;
        if (wq < 7) mq = __ldcg(&mp[(wq + 1)*BSZ + b]);
        unsigned wds[4] = {cur.x, cur.y, cur.z, cur.w};
#pragma unroll
        for (int wi = 0; wi < 4; wi++) {
            unsigned wd = wds[wi];
#pragma unroll
            for (int d = 0; d < 4; d++) {
#pragma unroll
                for (int c = 0; c < 4; c++) {
                    int k = wq*64 + wi*16 + d*4 + c;
                    unsigned long long u2 =
                        (wd & (1u << (8*d + c))) ? 0x3F8000003F800000ULL : 0ULL;
                    ulonglong2 wv = *(const ulonglong2*)&swm[k][0];
                    fma2(r01, u2, wv.x);
                    fma2(r23, u2, wv.y);
                }
            }
        }
    }
}

// ---------------- kernel: transpose x -> g_xT [t][i][b] -------------------
__global__ void k_tr(const float* __restrict__ x) {
    __shared__ float tile[32][33];
    int i0 = blockIdx.x * 32, b0 = blockIdx.y * 32, t = blockIdx.z;
    int tx = threadIdx.x, ty = threadIdx.y;
    int i = i0 + tx;
#pragma unroll
    for (int r = 0; r < 4; r++) {
        int b = b0 + ty + r*8;
        float v = 0.0f;
        if (i < INDIM) v = x[((size_t)b*T + t)*INDIM + i];
        tile[ty + r*8][tx] = v;
    }
    __syncthreads();
#pragma unroll
    for (int r = 0; r < 4; r++) {
        int il = ty + r*8;
        g_xT[((size_t)t*INP + i0 + il)*BSZ + b0 + tx] = tile[tx][il];
    }
}

// ---------------- kernel: transpose W1 -> g_W1T ---------------------------
__global__ void k_w1t(const float* __restrict__ W1) {
    int idx = blockIdx.x * 256 + threadIdx.x;
    if (idx < INP*H) {
        int i = idx >> 9, j = idx & 511;
        g_W1T[idx] = (i < INDIM) ? W1[j*INDIM + i] : 0.0f;
    }
}

// ---------------- kernel: init packed spike buffers + fire counter --------
__global__ void k_init() {
    int idx = blockIdx.x * 256 + threadIdx.x;
    if (idx == 0) g_cnt = 0.0f;
    if (idx < (2*8*BSZ*16)/4) {
        ((unsigned*)g_pb1)[idx] = 0u;
        ((unsigned*)g_pb2)[idx] = 0u;
        ((unsigned*)g_pb3)[idx] = 0u;
    }
}

// ---------------- kernel: xw1 = (x@W1^T ascending-k chain)+b_i2h1 ---------
// double-buffered smem; weights pre-duplicated as 64-bit pairs.
__global__ __launch_bounds__(256) void k_xw1(const float* __restrict__ b1) {
    __shared__ __align__(16) float xs[2][8*128];
    __shared__ __align__(16) unsigned long long ws2[2][8*128];
    int jg = blockIdx.x, t = blockIdx.y;
    int tid = threadIdx.x;
    int tx = tid & 15, ty = tid >> 4;

    unsigned long long acc2[8][4];
#pragma unroll
    for (int i = 0; i < 8; i++)
#pragma unroll
        for (int p = 0; p < 4; p++) acc2[i][p] = 0ULL;

#pragma unroll
    for (int r = 0; r < 4; r++) {
        int lin = r*256 + tid;
        int kk = lin >> 7, c = lin & 127;
        xs[0][lin] = g_xT[((size_t)t*INP + kk)*BSZ + c];
        float wv = g_W1T[kk*H + jg*128 + c];
        unsigned long long wd2;
        asm("mov.b64 %0, {%1, %1};" : "=l"(wd2) : "f"(wv));
        ws2[0][lin] = wd2;
    }
    __syncthreads();

    for (int it = 0; it < INP/8; it++) {
        int cur = it & 1, nxt = cur ^ 1;
        if (it < INP/8 - 1) {
            int k0 = (it + 1)*8;
#pragma unroll
            for (int r = 0; r < 4; r++) {
                int lin = r*256 + tid;
                int kk = lin >> 7, c = lin & 127;
                xs[nxt][lin] = g_xT[((size_t)t*INP + k0 + kk)*BSZ + c];
                float wv = g_W1T[(k0 + kk)*H + jg*128 + c];
                unsigned long long wd2;
                asm("mov.b64 %0, {%1, %1};" : "=l"(wd2) : "f"(wv));
                ws2[nxt][lin] = wd2;
            }
        }
#pragma unroll
        for (int kk = 0; kk < 8; kk++) {
            ulonglong2 xa = *(const ulonglong2*)&xs[cur][kk*128 + tx*8];
            ulonglong2 xb = *(const ulonglong2*)&xs[cur][kk*128 + tx*8 + 4];
            unsigned long long xp[4] = {xa.x, xa.y, xb.x, xb.y};
#pragma unroll
            for (int i = 0; i < 8; i++) {
                unsigned long long wd2 = ws2[cur][kk*128 + ty*8 + i];
#pragma unroll
                for (int p = 0; p < 4; p++)
                    fma2(acc2[i][p], xp[p], wd2);
            }
        }
        __syncthreads();
    }
#pragma unroll
    for (int i = 0; i < 8; i++) {
        int jcol = jg*128 + ty*8 + i;
        float bias = __ldg(&b1[jcol]);
#pragma unroll
        for (int p = 0; p < 4; p++) {
            float lo, hi;
            UNPACK2(lo, hi, acc2[i][p]);
            g_xw1[((size_t)t*H + jcol)*BSZ + tx*8 + 2*p]     = __fadd_rn(lo, bias);
            g_xw1[((size_t)t*H + jcol)*BSZ + tx*8 + 2*p + 1] = __fadd_rn(hi, bias);
        }
    }
}

// ---------------- persistent pipelined ALIF scan (5 warp-groups) ----------
// 128 CTAs x 640 threads. wg = tid>>7; b = tid&127.
// wg0=l1(t=s)  wg1=ri2+ALIF-l2(t=s-1)  wg3=rh2(t=s-1)
// wg2=ri3+ALIF-l3(t=s-2)  wg4=rh3(t=s-2).  rh via smem + mid-stage sync.
__global__ __launch_bounds__(640) void k_scan(
    const float* __restrict__ Wh1, const float* __restrict__ bh1,
    const float* __restrict__ Wi2, const float* __restrict__ Wh2,
    const float* __restrict__ bi2, const float* __restrict__ bh2,
    const float* __restrict__ Wi3, const float* __restrict__ Wh3,
    const float* __restrict__ bi3, const float* __restrict__ bh3,
    const float* __restrict__ ta1, const float* __restrict__ ta2,
    const float* __restrict__ ta3, const float* __restrict__ tm1,
    const float* __restrict__ tm2, const float* __restrict__ tm3,
    float* __restrict__ dout)
{
    __shared__ __align__(16) float sw[5][H][4];       // 40KB, [mat][k][jl]
    __shared__ __align__(16) float sm_rh2[BSZ][4];    // 2KB
    __shared__ __align__(16) float sm_rh3[BSZ][4];    // 2KB
    __shared__ float red[20];
    const int tid = threadIdx.x;
    const int wg  = tid >> 7;          // 0..4
    const int b   = tid & 127;
    const int j0  = blockIdx.x * 4;
    const int jgrp = blockIdx.x;
    const unsigned moff = (unsigned)(((jgrp >> 4)*BSZ + b)*16 + (jgrp & 15));

    for (int i = tid; i < 5*H*4; i += 640) {
        int m = i >> 11, rem = i & 2047, k = rem >> 2, jl = rem & 3;
        const float* W = (m==0)?Wh1:(m==1)?Wi2:(m==2)?Wh2:(m==3)?Wi3:Wh3;
        sw[m][k][jl] = W[(size_t)(j0 + jl)*H + k];
    }
    __syncthreads();

    // per-wg ALIF constants (only wg0..2 own a layer)
    float al[4], ro[4], omal[4], omro[4], bA[4], bB[4];
    if (wg < 3) {
        const float* tmv = (wg==0) ? tm1 : (wg==1) ? tm2 : tm3;
        const float* tav = (wg==0) ? ta1 : (wg==1) ? ta2 : ta3;
#pragma unroll
        for (int jl = 0; jl < 4; jl++) {
            int j = j0 + jl;
            al[jl] = exp_xla_fma(__fdiv_rn(-1.0f, __ldg(&tmv[j])));
            ro[jl] = exp_xla_fma(__fdiv_rn(-1.0f, __ldg(&tav[j])));
            omal[jl] = __fsub_rn(1.0f, al[jl]);
            omro[jl] = __fsub_rn(1.0f, ro[jl]);
            if (wg == 0)      { bA[jl] = __ldg(&bh1[j]); bB[jl] = 0.0f; }
            else if (wg == 1) { bA[jl] = __ldg(&bi2[j]); bB[jl] = __ldg(&bh2[j]); }
            else              { bA[jl] = __ldg(&bi3[j]); bB[jl] = __ldg(&bh3[j]); }
        }
    }

    float mS[4], bS[4], sS[4];
#pragma unroll
    for (int jl = 0; jl < 4; jl++) { mS[jl]=0.0f; bS[jl]=0.01f; sS[jl]=0.0f; }

    for (int s = 0; s < T + 2; s++) {
        unsigned long long i01 = 0ULL, i23 = 0ULL;   // this wg's dot result
        // ---- phase 1: dot streams ----
        if (wg == 0) {
            if (s < T) dot2(g_pb1[s & 1], b, sw[0], i01, i23);
        } else if (wg == 1) {
            if (s >= 1 && s <= T) dot2(g_pb1[s & 1], b, sw[1], i01, i23);
        } else if (wg == 3) {
            if (s >= 1 && s <= T) {
                dot2(g_pb2[(s-1) & 1], b, sw[2], i01, i23);
                float lo, hi;
                UNPACK2(lo, hi, i01); sm_rh2[b][0] = lo; sm_rh2[b][1] = hi;
                UNPACK2(lo, hi, i23); sm_rh2[b][2] = lo; sm_rh2[b][3] = hi;
            }
        } else if (wg == 2) {
            if (s >= 2) dot2(g_pb2[(s-1) & 1], b, sw[3], i01, i23);
        } else { // wg == 4
            if (s >= 2) {
                dot2(g_pb3[(s-2) & 1], b, sw[4], i01, i23);
                float lo, hi;
                UNPACK2(lo, hi, i01); sm_rh3[b][0] = lo; sm_rh3[b][1] = hi;
                UNPACK2(lo, hi, i23); sm_rh3[b][2] = lo; sm_rh3[b][3] = hi;
            }
        }
        __syncthreads();
        // ---- phase 2: ALIF + mask stores ----
        if (wg == 0) {
            if (s < T) {
                const int t = s;
                float rr[4];
                UNPACK2(rr[0], rr[1], i01);
                UNPACK2(rr[2], rr[3], i23);
                unsigned msk = 0;
#pragma unroll
                for (int jl = 0; jl < 4; jl++) {
                    int j = j0 + jl;
                    float a = __fadd_rn(__fadd_rn(
                        __ldg(&g_xw1[((size_t)t*H + j)*BSZ + b]), rr[jl]), bA[jl]);
                    ALIF(mS[jl], sS[jl], bS[jl], a,
                         al[jl], omal[jl], ro[jl], omro[jl]);
                    if (sS[jl] != 0.0f) msk |= (1u << jl);
                }
                __stcg(&g_pb1[(t+1) & 1][moff], (unsigned char)msk);
            }
        } else if (wg == 1) {
            if (s >= 1 && s <= T) {
                const int t = s - 1;
                float ri[4];
                UNPACK2(ri[0], ri[1], i01);
                UNPACK2(ri[2], ri[3], i23);
                unsigned msk = 0;
#pragma unroll
                for (int jl = 0; jl < 4; jl++) {
                    float a = __fadd_rn(__fadd_rn(__fadd_rn(ri[jl], bA[jl]),
                                                  sm_rh2[b][jl]), bB[jl]);
                    ALIF(mS[jl], sS[jl], bS[jl], a,
                         al[jl], omal[jl], ro[jl], omro[jl]);
                    if (sS[jl] != 0.0f) msk |= (1u << jl);
                }
                __stcg(&g_pb2[(t+1) & 1][moff], (unsigned char)msk);
            }
        } else if (wg == 2) {
            if (s >= 2) {
                const int t = s - 2;
                float ri[4];
                UNPACK2(ri[0], ri[1], i01);
                UNPACK2(ri[2], ri[3], i23);
                unsigned msk = 0;
#pragma unroll
                for (int jl = 0; jl < 4; jl++) {
                    int j = j0 + jl;
                    float a = __fadd_rn(__fadd_rn(__fadd_rn(ri[jl], bA[jl]),
                                                  sm_rh3[b][jl]), bB[jl]);
                    ALIF(mS[jl], sS[jl], bS[jl], a,
                         al[jl], omal[jl], ro[jl], omro[jl]);
                    if (sS[jl] != 0.0f) msk |= (1u << jl);
                    g_m3h[((size_t)t*H + j)*BSZ + b] = mS[jl];
                    dout[HID_OFF + ((size_t)b*T + t)*H + j] = sS[jl];
                }
                __stcg(&g_pb3[(t+1) & 1][moff], (unsigned char)msk);
            }
        }
        gbar();
    }

    // fire rate: wg0..2 hold final spike states (exact integer floats)
    float c = 0.0f;
    if (wg < 3) {
#pragma unroll
        for (int jl = 0; jl < 4; jl++) c += sS[jl];
    }
#pragma unroll
    for (int o = 16; o > 0; o >>= 1) c += __shfl_xor_sync(0xffffffffu, c, o);
    if ((tid & 31) == 0) red[tid >> 5] = c;
    __syncthreads();
    if (tid == 0) {
        float sm = 0.0f;
#pragma unroll
        for (int i = 0; i < 20; i++) sm += red[i];
        atomicAdd(&g_cnt, sm);
    }
    gbar();
    if (blockIdx.x == 0 && tid == 0)
        dout[FIRE_OFF] = *((volatile float*)&g_cnt) / 196608.0f;
}

// ---------------- kernel: output = (m3@Wo^T chain from 0) + bo ------------
__global__ __launch_bounds__(128) void k_out(const float* __restrict__ Wo,
                                             const float* __restrict__ bo,
                                             float* __restrict__ dout) {
    int t = blockIdx.x, b = threadIdx.x;
    float acc[NOUT];
#pragma unroll
    for (int o = 0; o < NOUT; o++) acc[o] = 0.0f;
    const float* mp = &g_m3h[(size_t)t*H*BSZ + b];
    for (int k = 0; k < H; k++) {
        float v = mp[(size_t)k*BSZ];
#pragma unroll
        for (int o = 0; o < NOUT; o++)
            acc[o] = __fmaf_rn(v, __ldg(&Wo[o*H + k]), acc[o]);
    }
#pragma unroll
    for (int o = 0; o < NOUT; o++)
        dout[((size_t)b*T + t)*NOUT + o] = __fadd_rn(acc[o], __ldg(&bo[o]));
}

// ---------------- launch ---------------------------------------------------
extern "C" void kernel_launch(void* const* d_in, const int* in_sizes, int n_in,
                              void* d_out, int out_size) {
    const float* x      = (const float*)d_in[0];
    const float* W_i2h1 = (const float*)d_in[1];  const float* b_i2h1 = (const float*)d_in[2];
    const float* W_h2h1 = (const float*)d_in[3];  const float* b_h2h1 = (const float*)d_in[4];
    const float* W_i2h2 = (const float*)d_in[5];  const float* b_i2h2 = (const float*)d_in[6];
    const float* W_h2h2 = (const float*)d_in[7];  const float* b_h2h2 = (const float*)d_in[8];
    const float* W_i2h3 = (const float*)d_in[9];  const float* b_i2h3 = (const float*)d_in[10];
    const float* W_h2h3 = (const float*)d_in[11]; const float* b_h2h3 = (const float*)d_in[12];
    const float* W_h2o  = (const float*)d_in[13]; const float* b_h2o  = (const float*)d_in[14];
    const float* ta1 = (const float*)d_in[15];
    const float* ta2 = (const float*)d_in[16];
    const float* ta3 = (const float*)d_in[17];
    const float* tm1 = (const float*)d_in[18];
    const float* tm2 = (const float*)d_in[19];
    const float* tm3 = (const float*)d_in[20];
    float* out = (float*)d_out;

    k_tr  <<<dim3(22, 4, 250), dim3(32, 8)>>>(x);
    k_w1t <<<(INP*H + 255)/256, 256>>>(W_i2h1);
    k_init<<<(2*8*BSZ*16/4 + 255)/256, 256>>>();
    k_xw1 <<<dim3(4, 250), 256>>>(b_i2h1);

    k_scan<<<NCTA, 640>>>(W_h2h1, b_h2h1,
                          W_i2h2, W_h2h2, b_i2h2, b_h2h2,
                          W_i2h3, W_h2h3, b_i2h3, b_h2h3,
                          ta1, ta2, ta3, tm1, tm2, tm3, out);

    k_out <<<250, 128>>>(W_h2o, b_h2o, out);
}